// round 6
// baseline (speedup 1.0000x reference)
#include <cuda_runtime.h>

#define NG  8     // graphs
#define NN  128   // nodes
#define DIM 128   // embedding dim
#define NE  128   // edge types
#define VEC 300   // word-vec dim

// ---- scratch (device globals; no allocations allowed) ----
__device__ __align__(16) float g_vacc[NG][NN][DIM];
__device__ __align__(16) float g_bvec[NG][NN][DIM];
__device__ int   g_parent[NG][NN];
__device__ int   g_ccount[NG][NN];
__device__ int   g_cdone[NG][NN];
__device__ int   g_onpath[NG][NN];
__device__ int   g_path[NG][NN];
__device__ int   g_plen[NG];
__device__ int   g_edges_eff[NN];
__device__ int   g_rootdone[NG];
__device__ float g_dscore;

// ---- acquire/release primitives ----
__device__ __forceinline__ int ld_acquire(const int* p) {
    int v;
    asm volatile("ld.acquire.gpu.global.u32 %0, [%1];" : "=r"(v) : "l"(p) : "memory");
    return v;
}
__device__ __forceinline__ void red_release_add(int* p, int v) {
    asm volatile("red.release.gpu.global.add.u32 [%0], %1;" :: "l"(p), "r"(v) : "memory");
}
__device__ __forceinline__ void red_release_addf(float* p, float v) {
    asm volatile("red.release.gpu.global.add.f32 [%0], %1;" :: "l"(p), "f"(v) : "memory");
}
// ALL lanes spin: every lane carries its own acquire edge (same-address load
// broadcasts -> one wavefront per poll).
__device__ __forceinline__ void wait_ge(const int* p, int need) {
    while (ld_acquire(p) < need) { }
    __syncwarp();
}
#define BAR64(id) asm volatile("bar.sync %0, 64;" :: "r"(id) : "memory")

// ---------------------------------------------------------------------------
// Streaming half-matvec over K rows: thread owns 4 output dims (d0=4*lane);
// W4[k * DIM/4] = W[k][d0..d0+3]. CH=8 double-buffer -> 16 LDG.128 in flight.
// ---------------------------------------------------------------------------
template<int K, int CH>
__device__ __forceinline__ void mv_stream(const float4* __restrict__ W4,
                                          const float* __restrict__ r,
                                          float4& m) {
    constexpr int STEP = 2 * CH;
    constexpr int NCH  = (K + STEP - 1) / STEP;
    float4 A[CH], B[CH];
#pragma unroll
    for (int i = 0; i < CH; ++i)
        A[i] = (i < K) ? W4[i * (DIM / 4)] : make_float4(0.f, 0.f, 0.f, 0.f);
#pragma unroll
    for (int o = 0; o < NCH; ++o) {
        const int kb = o * STEP, k2 = kb + CH, k3 = kb + STEP;
#pragma unroll
        for (int i = 0; i < CH; ++i)
            B[i] = (k2 + i < K) ? W4[(k2 + i) * (DIM / 4)] : make_float4(0.f, 0.f, 0.f, 0.f);
#pragma unroll
        for (int i = 0; i < CH; ++i)
            if (kb + i < K) {
                const float rk = r[kb + i];
                m.x += rk * A[i].x; m.y += rk * A[i].y;
                m.z += rk * A[i].z; m.w += rk * A[i].w;
            }
#pragma unroll
        for (int i = 0; i < CH; ++i)
            A[i] = (k3 + i < K) ? W4[(k3 + i) * (DIM / 4)] : make_float4(0.f, 0.f, 0.f, 0.f);
#pragma unroll
        for (int i = 0; i < CH; ++i)
            if (k2 + i < K) {
                const float rk = r[k2 + i];
                m.x += rk * B[i].x; m.y += rk * B[i].y;
                m.z += rk * B[i].z; m.w += rk * B[i].w;
            }
    }
}

__device__ __forceinline__ float warp_sum(float s) {
#pragma unroll
    for (int o = 16; o; o >>= 1) s += __shfl_down_sync(0xffffffffu, s, o);
    return s;
}
__device__ __forceinline__ float4 relu4(float4 v) {
    return make_float4(fmaxf(v.x, 0.f), fmaxf(v.y, 0.f), fmaxf(v.z, 0.f), fmaxf(v.w, 0.f));
}
__device__ __forceinline__ void prefetch_l1_half(const char* base, int c) {
    // 32KB = 256 lines / 32 lanes = 8 per lane
#pragma unroll
    for (int i = 0; i < 8; ++i)
        asm volatile("prefetch.global.L1 [%0];" :: "l"(base + ((c + (i << 5)) << 7)));
}

// ---------------------------------------------------------------------------
// Reset + structure kernel. Blocks 0..7: per-graph flags/structure (counts,
// parents, pos->root path). Blocks 8..71: zero g_vacc slices.
// ---------------------------------------------------------------------------
__global__ __launch_bounds__(128) void k_reset(const int* __restrict__ graphs,
                                               const int* __restrict__ edges,
                                               const int* __restrict__ posp) {
    const int t = threadIdx.x, b = blockIdx.x;
    if (b < NG) {
        const int g = b;
        const int pos = posp[0];
        g_ccount[g][t] = 0;
        g_cdone[g][t]  = 0;
        g_onpath[g][t] = 0;
        if (g == 0) g_edges_eff[t] = (t == pos) ? -1 : edges[t];
        if (t == 0) { g_rootdone[g] = 0; if (g == 0) g_dscore = 0.f; }
        __syncthreads();
        const int off = graphs[g * NN + t];
        const int par = (off == 0) ? -1 : (t + off);
        g_parent[g][t] = par;
        if (par >= 0) atomicAdd(&g_ccount[g][par], 1);
        if (t == 0) {
            int cur = pos, len = 0;
            while (len < NN) {
                g_path[g][len++] = cur;
                g_onpath[g][cur] = 1;
                const int o = graphs[g * NN + cur];
                if (o == 0) break;
                cur += o;
            }
            g_plen[g] = len;
        }
    } else {
        constexpr int SL = NG * NN * DIM / 64;   // floats per zero-block
        float4* dst = (float4*)((float*)g_vacc + (b - NG) * SL);
        for (int i = t; i < SL / 4; i += 128)
            dst[i] = make_float4(0.f, 0.f, 0.f, 0.f);
    }
}

// ---------------------------------------------------------------------------
// Fused main kernel: 256 blocks x 256 threads, 2 blocks/SM -> all resident.
// Block b: node n=b>>1, k-half p=b&1.
// Phase 0: 8-warp k-split of base[n] = vecs[data[n]] @ dW + db for the
//   block's 64-dim half (kept in shared). pos blocks emit d_score partials.
// Phase 1: warp (n, g=w, half p): prefetch W-half to L1, wait 2*ccount child
//   signals, form v-half, then store bvec half (path node) or half-matvec +
//   atomicAdd into parent vacc (half 0 carries the bias); release-signal.
// Phase 2: block b: graph g=b>>5, 4 rows x 2-warp pairs; each pair k-splits
//   the pos->root chain of matvecs, combining via named barriers, with L1
//   prefetch of the next step's weights.
// ---------------------------------------------------------------------------
__global__ __launch_bounds__(256, 2) void k_main(
        const int* __restrict__ data,  const float* __restrict__ vecs,
        const float* __restrict__ dW,  const float* __restrict__ db,
        const float* __restrict__ sdw, const float* __restrict__ sbias,
        const float* __restrict__ ew,  const float* __restrict__ ebias,
        const float* __restrict__ sew, const int* __restrict__ posp,
        float* __restrict__ out) {
    __shared__ __align__(16) float shv[304];
    __shared__ __align__(16) float part[8][64];
    __shared__ __align__(16) float sh_base[64];
    __shared__ __align__(16) float sh_r[8][64];
    __shared__ __align__(16) float spart[4][DIM];
    __shared__ __align__(16) float sr[4][DIM];
    const int t = threadIdx.x, w = t >> 5, c = t & 31;
    const int b = blockIdx.x;
    const int pos = posp[0];

    // ================= phase 0: base half (node n, dims [64p,64p+64)) ======
    {
        const int n = b >> 1, p = b & 1;
        const float* vr = vecs + (long long)data[n] * VEC;
        for (int i = t; i < VEC; i += 256) shv[i] = vr[i];
        __syncthreads();
        const int k0 = w * 38, k1 = (k0 + 38 < VEC) ? k0 + 38 : VEC;
        float2 acc = make_float2(0.f, 0.f);
        for (int k = k0; k < k1; ++k) {
            const float rv = shv[k];
            const float2 wv = *(const float2*)(dW + (long long)k * DIM + 64 * p + 2 * c);
            acc.x += rv * wv.x; acc.y += rv * wv.y;
        }
        part[w][2 * c] = acc.x; part[w][2 * c + 1] = acc.y;
        __syncthreads();
        if (w == 0) {
            float2 m = *(const float2*)(db + 64 * p + 2 * c);
#pragma unroll
            for (int ww = 0; ww < 8; ++ww) {
                m.x += part[ww][2 * c]; m.y += part[ww][2 * c + 1];
            }
            sh_base[2 * c] = m.x; sh_base[2 * c + 1] = m.y;
            if (n == pos) {
                const float2 s2 = *(const float2*)(sdw + 64 * p + 2 * c);
                float s = warp_sum(m.x * s2.x + m.y * s2.y);
                if (c == 0) {
                    if (p == 0) s += sbias[0];
                    red_release_addf(&g_dscore, s);
                }
            }
        }
        __syncthreads();   // sh_base ready; d_score add HB-before all signals below
    }

    // ================= phase 1: vector task (n, g=w, half p) ==============
    {
        const int n = b >> 1, p = b & 1;
        const int g = w;
        const int need2  = 2 * g_ccount[g][n];
        const int par    = g_parent[g][n];
        const int onpath = g_onpath[g][n];
        const int eid    = g_edges_eff[n];
        const float* Wh = ew + ((long long)eid * DIM + 64 * p) * DIM;  // rows [64p..)
        if (!onpath) prefetch_l1_half((const char*)Wh, c);
        if (need2 > 0) wait_ge(&g_cdone[g][n], need2);
        float2 v = make_float2(sh_base[2 * c], sh_base[2 * c + 1]);
        if (need2 > 0) {
            const float2 va = __ldcg((const float2*)&g_vacc[g][n][64 * p + 2 * c]);
            v.x += va.x; v.y += va.y;
        }
        if (onpath) {
            *(float2*)&g_bvec[g][n][64 * p + 2 * c] = v;
            __syncwarp();
            if (c == 0) {
                if (par >= 0) red_release_add(&g_cdone[g][par], 1);
                else          red_release_add(&g_rootdone[g], 1);
            }
        } else {
            if (need2 > 0) { v.x = fmaxf(v.x, 0.f); v.y = fmaxf(v.y, 0.f); }
            sh_r[w][2 * c] = v.x; sh_r[w][2 * c + 1] = v.y;
            __syncwarp();
            float4 m = (p == 0) ? *(const float4*)(ebias + eid * DIM + 4 * c)
                                : make_float4(0.f, 0.f, 0.f, 0.f);
            mv_stream<64, 8>((const float4*)(Wh + 4 * c), sh_r[w], m);
            float* dst = &g_vacc[g][par][4 * c];
            atomicAdd(dst + 0, m.x); atomicAdd(dst + 1, m.y);
            atomicAdd(dst + 2, m.z); atomicAdd(dst + 3, m.w);
            __syncwarp();
            if (c == 0) red_release_add(&g_cdone[g][par], 1);
        }
    }

    // ================= phase 2: matrix chains (g=b>>5, 4 rows x 2 warps) ===
    {
        const int g   = b >> 5;
        const int sub = b & 31;
        const int r   = w >> 1;        // local row 0..3
        const int q   = w & 1;         // k-half of the pair
        const int e   = sub * 4 + r;
        const int bid = r + 1;         // named barrier per pair
        prefetch_l1_half((const char*)(ew + ((long long)e * DIM + 64 * q) * DIM), c);
        wait_ge(&g_rootdone[g], 2);

        const int plen = g_plen[g];
        const int p0   = g_path[g][0];
        // step 0 input: own half of v(pos), relu if internal
        {
            float2 v = __ldcg((const float2*)&g_bvec[g][p0][64 * q + 2 * c]);
            if (g_ccount[g][p0] > 0) { v.x = fmaxf(v.x, 0.f); v.y = fmaxf(v.y, 0.f); }
            sr[r][64 * q + 2 * c] = v.x; sr[r][64 * q + 2 * c + 1] = v.y;
        }
        __syncwarp();
        float4 m = (q == 0) ? *(const float4*)(ebias + e * DIM + 4 * c)
                            : make_float4(0.f, 0.f, 0.f, 0.f);
        mv_stream<64, 8>((const float4*)(ew + ((long long)e * DIM + 64 * q) * DIM + 4 * c),
                         sr[r] + 64 * q, m);
        if (plen > 1)   // prefetch step-1 weights
            prefetch_l1_half((const char*)(ew +
                ((long long)g_edges_eff[g_path[g][1]] * DIM + 64 * q) * DIM), c);
        if (q == 1) *(float4*)&spart[r][4 * c] = m;
        BAR64(bid);
        if (q == 0) {
            const float4 pp = *(const float4*)&spart[r][4 * c];
            m.x += pp.x; m.y += pp.y; m.z += pp.z; m.w += pp.w;
        }

        for (int s = 1; s < plen; ++s) {
            const int a   = g_path[g][s];
            const int eid = g_edges_eff[a];
            if (q == 0) {   // full next input vector (4 dims/thread over 128)
                const float4 bv = __ldcg((const float4*)&g_bvec[g][a][4 * c]);
                const float4 rr = relu4(make_float4(bv.x + m.x, bv.y + m.y,
                                                    bv.z + m.z, bv.w + m.w));
                *(float4*)&sr[r][4 * c] = rr;
            }
            BAR64(bid);
            if (s + 1 < plen)   // prefetch next step's weights
                prefetch_l1_half((const char*)(ew +
                    ((long long)g_edges_eff[g_path[g][s + 1]] * DIM + 64 * q) * DIM), c);
            float4 acc = (q == 0) ? *(const float4*)(ebias + eid * DIM + 4 * c)
                                  : make_float4(0.f, 0.f, 0.f, 0.f);
            mv_stream<64, 8>((const float4*)(ew + ((long long)eid * DIM + 64 * q) * DIM + 4 * c),
                             sr[r] + 64 * q, acc);
            if (q == 1) *(float4*)&spart[r][4 * c] = acc;
            BAR64(bid);
            if (q == 0) {
                const float4 pp = *(const float4*)&spart[r][4 * c];
                m.x = acc.x + pp.x; m.y = acc.y + pp.y;
                m.z = acc.z + pp.z; m.w = acc.w + pp.w;
            }
        }

        if (q == 0) {
            const float4 s4 = *(const float4*)(sew + 4 * c);
            const float s = warp_sum(m.x * s4.x + m.y * s4.y + m.z * s4.z + m.w * s4.w);
            if (c == 0) out[g * NE + e] = __ldcg(&g_dscore) + s;
        }
    }
}

extern "C" void kernel_launch(void* const* d_in, const int* in_sizes, int n_in,
                              void* d_out, int out_size) {
    const int*   data   = (const int*)d_in[0];
    // d_in[1] = types (unused: single data_type)
    const int*   graphs = (const int*)d_in[2];
    const int*   edges  = (const int*)d_in[3];
    const int*   posp   = (const int*)d_in[4];
    const float* vecs   = (const float*)d_in[5];
    const float* dW     = (const float*)d_in[6];
    const float* db     = (const float*)d_in[7];
    const float* ew     = (const float*)d_in[8];
    const float* ebias  = (const float*)d_in[9];
    const float* sew    = (const float*)d_in[10];
    const float* sdw    = (const float*)d_in[11];
    const float* sbias  = (const float*)d_in[12];
    float* out = (float*)d_out;

    k_reset<<<NG + 64, 128>>>(graphs, edges, posp);
    k_main<<<2 * NN, 256>>>(data, vecs, dW, db, sdw, sbias,
                            ew, ebias, sew, posp, out);
}

// round 7
// speedup vs baseline: 1.1757x; 1.1757x over previous
#include <cuda_runtime.h>

#define NG  8     // graphs
#define NN  128   // nodes
#define DIM 128   // embedding dim
#define NE  128   // edge types
#define VEC 300   // word-vec dim

// ---- scratch (device globals; no allocations allowed) ----
__device__ __align__(16) float g_vacc[NG][NN][DIM];
__device__ __align__(16) float g_bvec[NG][NN][DIM];
__device__ int   g_parent[NG][NN];
__device__ int   g_ccount[NG][NN];
__device__ int   g_cdone[NG][NN];
__device__ int   g_onpath[NG][NN];
__device__ int   g_path[NG][NN];
__device__ int   g_plen[NG];
__device__ int   g_edges_eff[NN];
__device__ int   g_rootdone[NG];
__device__ float g_dscore;

// ---- acquire/release primitives ----
__device__ __forceinline__ int ld_acquire(const int* p) {
    int v;
    asm volatile("ld.acquire.gpu.global.u32 %0, [%1];" : "=r"(v) : "l"(p) : "memory");
    return v;
}
__device__ __forceinline__ void red_release_add(int* p, int v) {
    asm volatile("red.release.gpu.global.add.u32 [%0], %1;" :: "l"(p), "r"(v) : "memory");
}
// ALL lanes spin: every lane carries its own acquire edge.
__device__ __forceinline__ void wait_ge(const int* p, int need) {
    while (ld_acquire(p) < need) { }
    __syncwarp();
}

// ---------------------------------------------------------------------------
// Streaming matvec over K rows: thread owns 4 output dims; W4[k*DIM/4] =
// W[k][d0..d0+3]. CH-deep double buffer -> 2*CH LDG.128 in flight.
// ---------------------------------------------------------------------------
template<int K, int CH>
__device__ __forceinline__ void mv_stream(const float4* __restrict__ W4,
                                          const float* __restrict__ r,
                                          float4& m) {
    constexpr int STEP = 2 * CH;
    constexpr int NCH  = (K + STEP - 1) / STEP;
    float4 A[CH], B[CH];
#pragma unroll
    for (int i = 0; i < CH; ++i)
        A[i] = (i < K) ? W4[i * (DIM / 4)] : make_float4(0.f, 0.f, 0.f, 0.f);
#pragma unroll
    for (int o = 0; o < NCH; ++o) {
        const int kb = o * STEP, k2 = kb + CH, k3 = kb + STEP;
#pragma unroll
        for (int i = 0; i < CH; ++i)
            B[i] = (k2 + i < K) ? W4[(k2 + i) * (DIM / 4)] : make_float4(0.f, 0.f, 0.f, 0.f);
#pragma unroll
        for (int i = 0; i < CH; ++i)
            if (kb + i < K) {
                const float rk = r[kb + i];
                m.x += rk * A[i].x; m.y += rk * A[i].y;
                m.z += rk * A[i].z; m.w += rk * A[i].w;
            }
#pragma unroll
        for (int i = 0; i < CH; ++i)
            A[i] = (k3 + i < K) ? W4[(k3 + i) * (DIM / 4)] : make_float4(0.f, 0.f, 0.f, 0.f);
#pragma unroll
        for (int i = 0; i < CH; ++i)
            if (k2 + i < K) {
                const float rk = r[k2 + i];
                m.x += rk * B[i].x; m.y += rk * B[i].y;
                m.z += rk * B[i].z; m.w += rk * B[i].w;
            }
    }
}

__device__ __forceinline__ float warp_sum(float s) {
#pragma unroll
    for (int o = 16; o; o >>= 1) s += __shfl_down_sync(0xffffffffu, s, o);
    return s;
}
__device__ __forceinline__ float4 relu4(float4 v) {
    return make_float4(fmaxf(v.x, 0.f), fmaxf(v.y, 0.f), fmaxf(v.z, 0.f), fmaxf(v.w, 0.f));
}
// Cooperative 8-warp L1 prefetch of one 64KB matrix: warp w takes lines
// [w*64, w*64+64) -> 2 lines per lane.
__device__ __forceinline__ void prefetch_l1_slice(const char* base, int w, int c) {
    const char* p = base + (((w << 6) + c) << 7);
    asm volatile("prefetch.global.L1 [%0];" :: "l"(p));
    asm volatile("prefetch.global.L1 [%0];" :: "l"(p + (32 << 7)));
}

// ---------------------------------------------------------------------------
// Reset + structure kernel. Blocks 0..7: per-graph flags/structure (counts,
// parents, pos->root path). Blocks 8..71: zero g_vacc slices.
// ---------------------------------------------------------------------------
__global__ __launch_bounds__(128) void k_reset(const int* __restrict__ graphs,
                                               const int* __restrict__ edges,
                                               const int* __restrict__ posp) {
    const int t = threadIdx.x, b = blockIdx.x;
    if (b < NG) {
        const int g = b;
        const int pos = posp[0];
        g_ccount[g][t] = 0;
        g_cdone[g][t]  = 0;
        g_onpath[g][t] = 0;
        if (g == 0) g_edges_eff[t] = (t == pos) ? -1 : edges[t];
        if (t == 0) g_rootdone[g] = 0;
        __syncthreads();
        const int off = graphs[g * NN + t];
        const int par = (off == 0) ? -1 : (t + off);
        g_parent[g][t] = par;
        if (par >= 0) atomicAdd(&g_ccount[g][par], 1);
        if (t == 0) {
            int cur = pos, len = 0;
            while (len < NN) {
                g_path[g][len++] = cur;
                g_onpath[g][cur] = 1;
                const int o = graphs[g * NN + cur];
                if (o == 0) break;
                cur += o;
            }
            g_plen[g] = len;
        }
    } else {
        constexpr int SL = NG * NN * DIM / 64;   // floats per zero-block
        float4* dst = (float4*)((float*)g_vacc + (b - NG) * SL);
        for (int i = t; i < SL / 4; i += 128)
            dst[i] = make_float4(0.f, 0.f, 0.f, 0.f);
    }
}

// ---------------------------------------------------------------------------
// Fused main kernel: 128 blocks x 256 threads, 1 block/SM -> all resident.
// Phase 0: block n computes base[n] = vecs[data[n]] @ dW + db via 8-warp
//   k-split into shared sh_base. The pos block also stores d_score (made
//   visible through its phase-1 release signal; pos is path[0] of every
//   graph, so every rootdone acquire happens-after it).
// Phase 1: warp (block=n, g=w) owns tree task (n,g). All warps cooperatively
//   prefetch the block's shared W[edges[n]] (64KB) into L1 BEFORE the child
//   wait, so the post-wait matvec hits L1. Then: wait ccount signals, form
//   v = base + vacc, and either store bvec (path node) or matvec + atomicAdd
//   into the parent's vacc; release-signal the parent counter.
// Phase 2: warp (g=b>>4, row e=(b&15)*8+w) waits on rootdone, then walks the
//   pos->root chain of matvecs. Steps >=1 share W across the block's 8 row
//   warps: cooperative L1 prefetch of step s+1's W is issued before step s's
//   matvec. Step-0 per-row weights are L2-prefetched during the wait.
// ---------------------------------------------------------------------------
__global__ __launch_bounds__(256, 1) void k_main(
        const int* __restrict__ data,  const float* __restrict__ vecs,
        const float* __restrict__ dW,  const float* __restrict__ db,
        const float* __restrict__ sdw, const float* __restrict__ sbias,
        const float* __restrict__ ew,  const float* __restrict__ ebias,
        const float* __restrict__ sew, const int* __restrict__ posp,
        float* __restrict__ out) {
    __shared__ __align__(16) float shv[304];
    __shared__ __align__(16) float part[8][DIM];
    __shared__ __align__(16) float sh_base[DIM];
    __shared__ __align__(16) float shr[8][DIM];
    const int t = threadIdx.x, w = t >> 5, c = t & 31;
    const int d0 = c * 4;
    const int b = blockIdx.x;
    const int pos = posp[0];

    // ================= phase 0: base[n] for this block's node ==============
    {
        const int n = b;
        const float* vr = vecs + (long long)data[n] * VEC;
        for (int i = t; i < 304; i += 256) shv[i] = (i < VEC) ? vr[i] : 0.f;
        __syncthreads();
        const int k0 = (w * VEC) >> 3, k1 = ((w + 1) * VEC) >> 3;   // 37/38 rows
        float4 acc = make_float4(0.f, 0.f, 0.f, 0.f);
#pragma unroll 8
        for (int k = k0; k < k1; ++k) {
            const float rv = shv[k];
            const float4 wv = *(const float4*)(dW + (long long)k * DIM + d0);
            acc.x += rv * wv.x; acc.y += rv * wv.y;
            acc.z += rv * wv.z; acc.w += rv * wv.w;
        }
        *(float4*)&part[w][d0] = acc;
        __syncthreads();
        if (w == 0) {
            float4 m = *(const float4*)(db + d0);
#pragma unroll
            for (int ww = 0; ww < 8; ++ww) {
                const float4 p = *(const float4*)&part[ww][d0];
                m.x += p.x; m.y += p.y; m.z += p.z; m.w += p.w;
            }
            *(float4*)&sh_base[d0] = m;
            if (n == pos) {
                const float4 s4 = *(const float4*)(sdw + d0);
                const float s = warp_sum(m.x * s4.x + m.y * s4.y + m.z * s4.z + m.w * s4.w);
                if (c == 0) g_dscore = sbias[0] + s;   // ordered by release below
            }
        }
        __syncthreads();
    }

    // ================= phase 1: vector task (n = block, g = warp) ==========
    {
        const int n = b;
        const int g = w;
        const int need   = g_ccount[g][n];
        const int par    = g_parent[g][n];
        const int onpath = g_onpath[g][n];
        const int eid    = g_edges_eff[n];
        const float* W = ew + (long long)eid * DIM * DIM;
        if (eid >= 0)   // shared across all 8 warps; slice-prefetch into L1
            prefetch_l1_slice((const char*)W, w, c);
        if (need > 0) wait_ge(&g_cdone[g][n], need);
        float4 v = *(const float4*)&sh_base[d0];
        if (need > 0) {
            const float4 va = __ldcg((const float4*)&g_vacc[g][n][d0]);
            v.x += va.x; v.y += va.y; v.z += va.z; v.w += va.w;
        }
        if (onpath) {
            *(float4*)&g_bvec[g][n][d0] = v;
            __syncwarp();
            if (c == 0) {
                if (par >= 0) red_release_add(&g_cdone[g][par], 1);
                else          red_release_add(&g_rootdone[g], 1);
            }
        } else {
            if (need > 0) v = relu4(v);       // relu only for internal nodes
            *(float4*)&shr[w][d0] = v;
            __syncwarp();
            float4 m = *(const float4*)(ebias + eid * DIM + d0);
            mv_stream<DIM, 16>((const float4*)(W + d0), shr[w], m);
            float* dst = &g_vacc[g][par][d0];
            atomicAdd(dst + 0, m.x); atomicAdd(dst + 1, m.y);
            atomicAdd(dst + 2, m.z); atomicAdd(dst + 3, m.w);
            __syncwarp();
            if (c == 0) red_release_add(&g_cdone[g][par], 1);
        }
        __syncwarp();
    }

    // ================= phase 2: matrix chain (g = b>>4, row e) =============
    {
        const int g = b >> 4;
        const int e = (b & 15) * 8 + w;
        {
            // warm L2 with this row's step-0 weights while waiting
            const char* wb = (const char*)(ew + (long long)e * DIM * DIM);
#pragma unroll
            for (int i = 0; i < 16; ++i)
                asm volatile("prefetch.global.L2 [%0];" :: "l"(wb + ((c + (i << 5)) << 7)));
        }
        wait_ge(&g_rootdone[g], 1);

        const int plen = g_plen[g];
        const int p0   = g_path[g][0];

        float4 r0 = __ldcg((const float4*)&g_bvec[g][p0][d0]);
        if (g_ccount[g][p0] > 0) r0 = relu4(r0);
        *(float4*)&shr[w][d0] = r0;
        __syncwarp();

        // step 0: per-row weight matrix W[e]; prefetch step-1 shared W to L1
        if (plen > 1)
            prefetch_l1_slice((const char*)(ew +
                (long long)g_edges_eff[g_path[g][1]] * DIM * DIM), w, c);
        float4 m = *(const float4*)(ebias + e * DIM + d0);
        mv_stream<DIM, 16>((const float4*)(ew + (long long)e * DIM * DIM + d0), shr[w], m);

        // steps 1..plen-1: shared weight matrix per (graph, step)
        for (int s = 1; s < plen; ++s) {
            const int a = g_path[g][s];
            const float4 bv = __ldcg((const float4*)&g_bvec[g][a][d0]);
            const float4 r = make_float4(fmaxf(bv.x + m.x, 0.f), fmaxf(bv.y + m.y, 0.f),
                                         fmaxf(bv.z + m.z, 0.f), fmaxf(bv.w + m.w, 0.f));
            __syncwarp();                      // all lanes done reading prior shr
            *(float4*)&shr[w][d0] = r;
            __syncwarp();
            const int eid = g_edges_eff[a];
            if (s + 1 < plen)                  // prefetch next step's shared W
                prefetch_l1_slice((const char*)(ew +
                    (long long)g_edges_eff[g_path[g][s + 1]] * DIM * DIM), w, c);
            m = *(const float4*)(ebias + eid * DIM + d0);
            mv_stream<DIM, 16>((const float4*)(ew + (long long)eid * DIM * DIM + d0), shr[w], m);
        }

        const float4 s4 = *(const float4*)(sew + d0);
        const float s = warp_sum(m.x * s4.x + m.y * s4.y + m.z * s4.z + m.w * s4.w);
        if (c == 0) out[g * NE + e] = __ldcg(&g_dscore) + s;
    }
}

extern "C" void kernel_launch(void* const* d_in, const int* in_sizes, int n_in,
                              void* d_out, int out_size) {
    const int*   data   = (const int*)d_in[0];
    // d_in[1] = types (unused: single data_type)
    const int*   graphs = (const int*)d_in[2];
    const int*   edges  = (const int*)d_in[3];
    const int*   posp   = (const int*)d_in[4];
    const float* vecs   = (const float*)d_in[5];
    const float* dW     = (const float*)d_in[6];
    const float* db     = (const float*)d_in[7];
    const float* ew     = (const float*)d_in[8];
    const float* ebias  = (const float*)d_in[9];
    const float* sew    = (const float*)d_in[10];
    const float* sdw    = (const float*)d_in[11];
    const float* sbias  = (const float*)d_in[12];
    float* out = (float*)d_out;

    k_reset<<<NG + 64, 128>>>(graphs, edges, posp);
    k_main<<<NN, 256>>>(data, vecs, dW, db, sdw, sbias,
                        ew, ebias, sew, posp, out);
}